// round 12
// baseline (speedup 1.0000x reference)
#include <cuda_runtime.h>
#include <cuda_fp16.h>
#include <cstdint>

#define SEQ   2048
#define BATCH 64
#define DIM   512
#define HID   512
#define GATE  2048   // 4*HID
#define NG    4      // independent batch groups (= clusters)
#define GSZ   16     // CTAs per group (= cluster size)
#define BPG   16     // batches per group

// ---------------- device scratch ---------------------------------------------
__device__ float  g_xg[(size_t)SEQ * BATCH * GATE];  // precomputed input gates
__device__ __half g_hh[2][BATCH * HID];              // double-buffered hidden state (fp16)

struct alignas(128) PadU { unsigned v; unsigned pad[31]; };
__device__ PadU g_cnt[NG];   // fallback barrier: per-group arrive counters
__device__ PadU g_gen[NG];   // fallback barrier: per-group generation (monotonic)

// ---------------- helpers ----------------------------------------------------
__device__ __forceinline__ uint32_t pack_h2(float a, float b) {
    __half2 h = __floats2half2_rn(a, b);
    return *reinterpret_cast<uint32_t*>(&h);
}
__device__ __forceinline__ uint32_t ldcg_u32(const void* p) {
    uint32_t v;
    asm volatile("ld.global.cg.b32 %0, [%1];" : "=r"(v) : "l"(p));
    return v;
}
__device__ __forceinline__ void mma_f16(float* c, const uint32_t* a, const uint32_t* b) {
    asm volatile(
        "mma.sync.aligned.m16n8k16.row.col.f32.f16.f16.f32 "
        "{%0,%1,%2,%3}, {%4,%5,%6,%7}, {%8,%9}, {%0,%1,%2,%3};"
        : "+f"(c[0]), "+f"(c[1]), "+f"(c[2]), "+f"(c[3])
        : "r"(a[0]), "r"(a[1]), "r"(a[2]), "r"(a[3]), "r"(b[0]), "r"(b[1]));
}
__device__ __forceinline__ float sigf(float x) { return 1.0f / (1.0f + __expf(-x)); }
__device__ __forceinline__ float tanhfast(float x) { return 2.0f / (1.0f + __expf(-2.0f * x)) - 1.0f; }

// =============================================================================
// Phase 1: Xg = x @ W_ih^T + (b_ih + b_hh)   (unchanged — proven)
// =============================================================================
__global__ __launch_bounds__(256) void lstm_xgemm(
    const float* __restrict__ x, const float* __restrict__ Wih,
    const float* __restrict__ bih, const float* __restrict__ bhh)
{
    __shared__ __half As[128 * 40];
    __shared__ __half Bs[128 * 40];
    __shared__ float  bsum[128];

    const int t = threadIdx.x;
    const int warp = t >> 5, lane = t & 31;
    const int wm = warp & 1;
    const int wn = warp >> 1;
    const int g = lane >> 2, tig = lane & 3;
    const int m0 = blockIdx.y * 128;
    const int n0 = blockIdx.x * 128;

    if (t < 128) bsum[t] = bih[n0 + t] + bhh[n0 + t];

    float acc[4][4][4];
#pragma unroll
    for (int mt = 0; mt < 4; mt++)
#pragma unroll
        for (int nt = 0; nt < 4; nt++)
#pragma unroll
            for (int i = 0; i < 4; i++) acc[mt][nt][i] = 0.f;

    for (int kc = 0; kc < 512; kc += 32) {
        __syncthreads();
#pragma unroll
        for (int i = 0; i < 4; i++) {
            int f = t + i * 256;
            int row = f >> 3, q = (f & 7) * 4;
            float4 v = *reinterpret_cast<const float4*>(x + (size_t)(m0 + row) * 512 + kc + q);
            __half2* d = reinterpret_cast<__half2*>(As + row * 40 + q);
            d[0] = __floats2half2_rn(v.x, v.y);
            d[1] = __floats2half2_rn(v.z, v.w);
        }
#pragma unroll
        for (int i = 0; i < 4; i++) {
            int f = t + i * 256;
            int row = f >> 3, q = (f & 7) * 4;
            float4 v = *reinterpret_cast<const float4*>(Wih + (size_t)(n0 + row) * 512 + kc + q);
            __half2* d = reinterpret_cast<__half2*>(Bs + row * 40 + q);
            d[0] = __floats2half2_rn(v.x, v.y);
            d[1] = __floats2half2_rn(v.z, v.w);
        }
        __syncthreads();

#pragma unroll
        for (int kt = 0; kt < 2; kt++) {
            const int k0 = kt * 16;
            uint32_t a[4][4], b[4][2];
#pragma unroll
            for (int mt = 0; mt < 4; mt++) {
                const int r = wm * 64 + mt * 16;
                a[mt][0] = *reinterpret_cast<const uint32_t*>(As + (r + g)     * 40 + k0 + 2 * tig);
                a[mt][1] = *reinterpret_cast<const uint32_t*>(As + (r + g + 8) * 40 + k0 + 2 * tig);
                a[mt][2] = *reinterpret_cast<const uint32_t*>(As + (r + g)     * 40 + k0 + 2 * tig + 8);
                a[mt][3] = *reinterpret_cast<const uint32_t*>(As + (r + g + 8) * 40 + k0 + 2 * tig + 8);
            }
#pragma unroll
            for (int nt = 0; nt < 4; nt++) {
                const int rn = wn * 32 + nt * 8;
                b[nt][0] = *reinterpret_cast<const uint32_t*>(Bs + (rn + g) * 40 + k0 + 2 * tig);
                b[nt][1] = *reinterpret_cast<const uint32_t*>(Bs + (rn + g) * 40 + k0 + 2 * tig + 8);
            }
#pragma unroll
            for (int mt = 0; mt < 4; mt++)
#pragma unroll
                for (int nt = 0; nt < 4; nt++)
                    mma_f16(acc[mt][nt], a[mt], b[nt]);
        }
    }

#pragma unroll
    for (int mt = 0; mt < 4; mt++) {
        const int r0 = m0 + wm * 64 + mt * 16 + g;
#pragma unroll
        for (int nt = 0; nt < 4; nt++) {
            const int cl = wn * 32 + nt * 8 + 2 * tig;
            const float b0 = bsum[cl], b1 = bsum[cl + 1];
            float2 v0 = make_float2(acc[mt][nt][0] + b0, acc[mt][nt][1] + b1);
            float2 v1 = make_float2(acc[mt][nt][2] + b0, acc[mt][nt][3] + b1);
            *reinterpret_cast<float2*>(g_xg + (size_t)r0 * GATE + n0 + cl)       = v0;
            *reinterpret_cast<float2*>(g_xg + (size_t)(r0 + 8) * GATE + n0 + cl) = v1;
        }
    }
}

// =============================================================================
// Phase 2: batch-partitioned persistent recurrence.
// 4 groups x 16 CTAs (group == HW cluster when available).
// Warp split: 4-way M x 2-way K. Warp w: m-quarter mq=w&3 (packed rows
// [32mq, 32mq+32)), k-half kh=w>>2 (K slice [256kh, 256kh+256)).
// Only a 2-way k-partial reduce through smem (18 KB store + 18 KB read).
// =============================================================================
__device__ __forceinline__ void gbar_flag(int bg) {
    __syncthreads();
    if (threadIdx.x == 0) {
        unsigned* cnt = &g_cnt[bg].v;
        unsigned* gen = &g_gen[bg].v;
        unsigned gv;
        asm volatile("ld.acquire.gpu.global.u32 %0, [%1];" : "=r"(gv) : "l"(gen) : "memory");
        unsigned old;
        asm volatile("atom.acq_rel.gpu.global.add.u32 %0, [%1], %2;"
                     : "=r"(old) : "l"(cnt), "r"(1u) : "memory");
        if (old == GSZ - 1u) {
            asm volatile("st.relaxed.gpu.global.u32 [%0], %1;" :: "l"(cnt), "r"(0u) : "memory");
            asm volatile("st.release.gpu.global.u32 [%0], %1;" :: "l"(gen), "r"(gv + 1u) : "memory");
        } else {
            unsigned cur;
            while (true) {
                asm volatile("ld.acquire.gpu.global.u32 %0, [%1];" : "=r"(cur) : "l"(gen) : "memory");
                if (cur != gv) break;
                __nanosleep(40);
            }
        }
    }
    __syncthreads();
}

template<bool CLUSTER>
__global__ __launch_bounds__(256, 1) void lstm_rec5(const float* __restrict__ Whh,
                                                    float* __restrict__ out)
{
    __shared__ float part[2 * 128 * 18];   // 18432 B: two k-half partial planes
    const int t = threadIdx.x, w = t >> 5, lane = t & 31;
    const int g = lane >> 2, tig = lane & 3;
    const int bg  = blockIdx.x >> 4;        // batch group 0..3
    const int C0  = (blockIdx.x & 15) * 32; // h-col base
    const int NB0 = bg * BPG;               // batch base
    const int mq  = w & 3;                  // m-quarter 0..3
    const int kh  = w >> 2;                 // k-half 0..1
    const int ks  = kh * 256;               // this warp's k-slice base

    // ---- resident W_hh fragments: rows [32mq, 32mq+32), K slice 256 ----
    // packed row r = q*32 + j  <->  W_hh[q*512 + C0 + j]   (q = gate, j = col)
    uint32_t wfr[2][16][4];                 // [mtile][ktile][reg] = 128 regs
#pragma unroll
    for (int mt = 0; mt < 2; mt++) {
        const int row_lo = 32 * mq + 16 * mt + g;
        const int row_hi = row_lo + 8;
        const float* wlo = Whh + (size_t)((row_lo >> 5) * 512 + C0 + (row_lo & 31)) * 512;
        const float* whi = Whh + (size_t)((row_hi >> 5) * 512 + C0 + (row_hi & 31)) * 512;
#pragma unroll
        for (int kt = 0; kt < 16; kt++) {
            const int k = ks + kt * 16 + 2 * tig;
            wfr[mt][kt][0] = pack_h2(wlo[k],     wlo[k + 1]);
            wfr[mt][kt][1] = pack_h2(whi[k],     whi[k + 1]);
            wfr[mt][kt][2] = pack_h2(wlo[k + 8], wlo[k + 9]);
            wfr[mt][kt][3] = pack_h2(whi[k + 8], whi[k + 9]);
        }
    }

    // output mapping: thread owns (batch cb, col pair cp)
    const int cb = t >> 4;                  // 0..15 local batch
    const int cp = t & 15;                  // 0..15 col pair
    const int gb = NB0 + cb;                // global batch
    const int gc = C0 + 2 * cp;             // global h-col

    *reinterpret_cast<uint32_t*>(&g_hh[0][gb * HID + gc]) = 0u;
    float c0 = 0.f, c1 = 0.f, hv0 = 0.f, hv1 = 0.f;

    // Xg prefetch for step 0
    float xg[4][2];
    {
        const float* xb = g_xg + (size_t)gb * GATE + gc;
#pragma unroll
        for (int q = 0; q < 4; q++) {
            float2 u = *reinterpret_cast<const float2*>(xb + q * 512);
            xg[q][0] = u.x; xg[q][1] = u.y;
        }
    }

    if (CLUSTER) {
        __syncthreads();
        asm volatile("barrier.cluster.arrive.aligned;" ::: "memory");
        asm volatile("barrier.cluster.wait.aligned;" ::: "memory");
    } else {
        gbar_flag(bg);
    }

    int p = 0;
    for (int s = 0; s < SEQ; s++) {
        const __half* hsrc = g_hh[p];

        float acc[2][2][4];
#pragma unroll
        for (int mt = 0; mt < 2; mt++)
#pragma unroll
            for (int nt = 0; nt < 2; nt++)
#pragma unroll
                for (int i = 0; i < 4; i++) acc[mt][nt][i] = 0.f;

        // ---- pipelined B-frag loads + mma over 16 k-tiles ----
        uint32_t bb[2][2][2];   // [buf][nt][reg]
#pragma unroll
        for (int nt = 0; nt < 2; nt++) {
            const __half* hp = hsrc + (size_t)(NB0 + nt * 8 + g) * HID + ks + 2 * tig;
            bb[0][nt][0] = ldcg_u32(hp);
            bb[0][nt][1] = ldcg_u32(hp + 8);
        }
#pragma unroll
        for (int kt = 0; kt < 16; kt++) {
            const int cur = kt & 1;
            if (kt < 15) {
#pragma unroll
                for (int nt = 0; nt < 2; nt++) {
                    const __half* hp = hsrc + (size_t)(NB0 + nt * 8 + g) * HID
                                     + ks + (kt + 1) * 16 + 2 * tig;
                    bb[cur ^ 1][nt][0] = ldcg_u32(hp);
                    bb[cur ^ 1][nt][1] = ldcg_u32(hp + 8);
                }
            }
#pragma unroll
            for (int mt = 0; mt < 2; mt++)
#pragma unroll
                for (int nt = 0; nt < 2; nt++)
                    mma_f16(acc[mt][nt], wfr[mt][kt], bb[cur][nt]);
        }

        // ---- store k-partials: plane[kh] [row 128][batch 16 pad 18] ----
        float* pw = part + kh * (128 * 18);
#pragma unroll
        for (int mt = 0; mt < 2; mt++)
#pragma unroll
            for (int nt = 0; nt < 2; nt++) {
                const int row = 32 * mq + 16 * mt + g, col = nt * 8 + 2 * tig;
                *reinterpret_cast<float2*>(pw + row * 18 + col) =
                    make_float2(acc[mt][nt][0], acc[mt][nt][1]);
                *reinterpret_cast<float2*>(pw + (row + 8) * 18 + col) =
                    make_float2(acc[mt][nt][2], acc[mt][nt][3]);
            }
        __syncthreads();

        // ---- 2-way reduce + activations + state update ----
        float sg[4][2];
#pragma unroll
        for (int q = 0; q < 4; q++)
#pragma unroll
            for (int jj = 0; jj < 2; jj++) {
                const int base = (q * 32 + 2 * cp + jj) * 18 + cb;
                sg[q][jj] = part[base] + part[128 * 18 + base];
            }

        const float i0 = sigf(xg[0][0] + sg[0][0]);
        const float i1 = sigf(xg[0][1] + sg[0][1]);
        const float f0 = sigf(xg[1][0] + sg[1][0]);
        const float f1 = sigf(xg[1][1] + sg[1][1]);
        const float g0 = tanhfast(xg[2][0] + sg[2][0]);
        const float g1 = tanhfast(xg[2][1] + sg[2][1]);
        const float o0 = sigf(xg[3][0] + sg[3][0]);
        const float o1 = sigf(xg[3][1] + sg[3][1]);

        c0 = f0 * c0 + i0 * g0;
        c1 = f1 * c1 + i1 * g1;
        hv0 = o0 * tanhfast(c0);
        hv1 = o1 * tanhfast(c1);

        // publish h first (must precede arrive), then hide DRAM work in the wait
        *reinterpret_cast<uint32_t*>(&g_hh[p ^ 1][gb * HID + gc]) = pack_h2(hv0, hv1);

        if (CLUSTER) {
            __syncthreads();   // all CTA threads done with part[] and published h
            asm volatile("barrier.cluster.arrive.aligned;" ::: "memory");
            // ---- hidden in barrier wait: out store + next-step Xg prefetch ----
            *reinterpret_cast<float2*>(out + ((size_t)s * BATCH + gb) * HID + gc) =
                make_float2(hv0, hv1);
            if (s + 1 < SEQ) {
                const float* xb = g_xg + ((size_t)(s + 1) * BATCH + gb) * GATE + gc;
#pragma unroll
                for (int q = 0; q < 4; q++) {
                    float2 u = *reinterpret_cast<const float2*>(xb + q * 512);
                    xg[q][0] = u.x; xg[q][1] = u.y;
                }
            }
            asm volatile("barrier.cluster.wait.aligned;" ::: "memory");
        } else {
            *reinterpret_cast<float2*>(out + ((size_t)s * BATCH + gb) * HID + gc) =
                make_float2(hv0, hv1);
            if (s + 1 < SEQ) {
                const float* xb = g_xg + ((size_t)(s + 1) * BATCH + gb) * GATE + gc;
#pragma unroll
                for (int q = 0; q < 4; q++) {
                    float2 u = *reinterpret_cast<const float2*>(xb + q * 512);
                    xg[q][0] = u.x; xg[q][1] = u.y;
                }
            }
            gbar_flag(bg);
        }
        p ^= 1;
    }

    // finals
    float* hf = out + (size_t)SEQ * BATCH * HID;
    float* cf = hf + (size_t)BATCH * HID;
    *reinterpret_cast<float2*>(hf + gb * HID + gc) = make_float2(hv0, hv1);
    *reinterpret_cast<float2*>(cf + gb * HID + gc) = make_float2(c0, c1);
}

// =============================================================================
extern "C" void kernel_launch(void* const* d_in, const int* in_sizes, int n_in,
                              void* d_out, int out_size) {
    const float* x   = (const float*)d_in[0];
    const float* Wih = (const float*)d_in[1];
    const float* Whh = (const float*)d_in[2];
    const float* bih = (const float*)d_in[3];
    const float* bhh = (const float*)d_in[4];
    float* out = (float*)d_out;

    dim3 grid1(16, 1024);
    lstm_xgemm<<<grid1, 256>>>(x, Wih, bih, bhh);

    // Deterministic cluster capability check (same result every call).
    int maxc = 0;
    cudaError_t e = cudaFuncSetAttribute(lstm_rec5<true>,
                                         cudaFuncAttributeNonPortableClusterSizeAllowed, 1);
    if (e == cudaSuccess) {
        cudaLaunchConfig_t qcfg = {};
        qcfg.gridDim = dim3(NG * GSZ, 1, 1);
        qcfg.blockDim = dim3(256, 1, 1);
        qcfg.dynamicSmemBytes = 0;
        if (cudaOccupancyMaxPotentialClusterSize(&maxc, lstm_rec5<true>, &qcfg) != cudaSuccess)
            maxc = 0;
    }

    if (maxc >= GSZ) {
        cudaLaunchConfig_t cfg = {};
        cfg.gridDim = dim3(NG * GSZ, 1, 1);
        cfg.blockDim = dim3(256, 1, 1);
        cfg.dynamicSmemBytes = 0;
        cudaLaunchAttribute attrs[1];
        attrs[0].id = cudaLaunchAttributeClusterDimension;
        attrs[0].val.clusterDim.x = GSZ;
        attrs[0].val.clusterDim.y = 1;
        attrs[0].val.clusterDim.z = 1;
        cfg.attrs = attrs;
        cfg.numAttrs = 1;
        cudaLaunchKernelEx(&cfg, lstm_rec5<true>, Whh, out);
    } else {
        lstm_rec5<false><<<NG * GSZ, 256>>>(Whh, out);
    }
}

// round 14
// speedup vs baseline: 1.0462x; 1.0462x over previous
#include <cuda_runtime.h>
#include <cuda_fp16.h>
#include <cstdint>

#define SEQ   2048
#define BATCH 64
#define DIM   512
#define HID   512
#define GATE  2048   // 4*HID
#define NG    8      // independent batch groups (= clusters)
#define GSZ   16     // CTAs per group (= cluster size)
#define BPG   8      // batches per group
#define PPAD  10     // partial-plane column pad (8 batches -> 10)

// ---------------- device scratch ---------------------------------------------
__device__ float  g_xg[(size_t)SEQ * BATCH * GATE];  // precomputed input gates
__device__ __half g_hh[2][BATCH * HID];              // double-buffered hidden state (fp16)

struct alignas(128) PadU { unsigned v; unsigned pad[31]; };
__device__ PadU g_cnt[NG];   // fallback barrier: per-group arrive counters
__device__ PadU g_gen[NG];   // fallback barrier: per-group generation (monotonic)

// ---------------- helpers ----------------------------------------------------
__device__ __forceinline__ uint32_t pack_h2(float a, float b) {
    __half2 h = __floats2half2_rn(a, b);
    return *reinterpret_cast<uint32_t*>(&h);
}
__device__ __forceinline__ uint32_t ldcg_u32(const void* p) {
    uint32_t v;
    asm volatile("ld.global.cg.b32 %0, [%1];" : "=r"(v) : "l"(p));
    return v;
}
__device__ __forceinline__ void mma_f16(float* c, const uint32_t* a, const uint32_t* b) {
    asm volatile(
        "mma.sync.aligned.m16n8k16.row.col.f32.f16.f16.f32 "
        "{%0,%1,%2,%3}, {%4,%5,%6,%7}, {%8,%9}, {%0,%1,%2,%3};"
        : "+f"(c[0]), "+f"(c[1]), "+f"(c[2]), "+f"(c[3])
        : "r"(a[0]), "r"(a[1]), "r"(a[2]), "r"(a[3]), "r"(b[0]), "r"(b[1]));
}
__device__ __forceinline__ float sigf(float x) { return 1.0f / (1.0f + __expf(-x)); }
__device__ __forceinline__ float tanhfast(float x) { return 2.0f / (1.0f + __expf(-2.0f * x)) - 1.0f; }

// =============================================================================
// Phase 1: Xg = x @ W_ih^T + (b_ih + b_hh)   (unchanged — proven)
// =============================================================================
__global__ __launch_bounds__(256) void lstm_xgemm(
    const float* __restrict__ x, const float* __restrict__ Wih,
    const float* __restrict__ bih, const float* __restrict__ bhh)
{
    __shared__ __half As[128 * 40];
    __shared__ __half Bs[128 * 40];
    __shared__ float  bsum[128];

    const int t = threadIdx.x;
    const int warp = t >> 5, lane = t & 31;
    const int wm = warp & 1;
    const int wn = warp >> 1;
    const int g = lane >> 2, tig = lane & 3;
    const int m0 = blockIdx.y * 128;
    const int n0 = blockIdx.x * 128;

    if (t < 128) bsum[t] = bih[n0 + t] + bhh[n0 + t];

    float acc[4][4][4];
#pragma unroll
    for (int mt = 0; mt < 4; mt++)
#pragma unroll
        for (int nt = 0; nt < 4; nt++)
#pragma unroll
            for (int i = 0; i < 4; i++) acc[mt][nt][i] = 0.f;

    for (int kc = 0; kc < 512; kc += 32) {
        __syncthreads();
#pragma unroll
        for (int i = 0; i < 4; i++) {
            int f = t + i * 256;
            int row = f >> 3, q = (f & 7) * 4;
            float4 v = *reinterpret_cast<const float4*>(x + (size_t)(m0 + row) * 512 + kc + q);
            __half2* d = reinterpret_cast<__half2*>(As + row * 40 + q);
            d[0] = __floats2half2_rn(v.x, v.y);
            d[1] = __floats2half2_rn(v.z, v.w);
        }
#pragma unroll
        for (int i = 0; i < 4; i++) {
            int f = t + i * 256;
            int row = f >> 3, q = (f & 7) * 4;
            float4 v = *reinterpret_cast<const float4*>(Wih + (size_t)(n0 + row) * 512 + kc + q);
            __half2* d = reinterpret_cast<__half2*>(Bs + row * 40 + q);
            d[0] = __floats2half2_rn(v.x, v.y);
            d[1] = __floats2half2_rn(v.z, v.w);
        }
        __syncthreads();

#pragma unroll
        for (int kt = 0; kt < 2; kt++) {
            const int k0 = kt * 16;
            uint32_t a[4][4], b[4][2];
#pragma unroll
            for (int mt = 0; mt < 4; mt++) {
                const int r = wm * 64 + mt * 16;
                a[mt][0] = *reinterpret_cast<const uint32_t*>(As + (r + g)     * 40 + k0 + 2 * tig);
                a[mt][1] = *reinterpret_cast<const uint32_t*>(As + (r + g + 8) * 40 + k0 + 2 * tig);
                a[mt][2] = *reinterpret_cast<const uint32_t*>(As + (r + g)     * 40 + k0 + 2 * tig + 8);
                a[mt][3] = *reinterpret_cast<const uint32_t*>(As + (r + g + 8) * 40 + k0 + 2 * tig + 8);
            }
#pragma unroll
            for (int nt = 0; nt < 4; nt++) {
                const int rn = wn * 32 + nt * 8;
                b[nt][0] = *reinterpret_cast<const uint32_t*>(Bs + (rn + g) * 40 + k0 + 2 * tig);
                b[nt][1] = *reinterpret_cast<const uint32_t*>(Bs + (rn + g) * 40 + k0 + 2 * tig + 8);
            }
#pragma unroll
            for (int mt = 0; mt < 4; mt++)
#pragma unroll
                for (int nt = 0; nt < 4; nt++)
                    mma_f16(acc[mt][nt], a[mt], b[nt]);
        }
    }

#pragma unroll
    for (int mt = 0; mt < 4; mt++) {
        const int r0 = m0 + wm * 64 + mt * 16 + g;
#pragma unroll
        for (int nt = 0; nt < 4; nt++) {
            const int cl = wn * 32 + nt * 8 + 2 * tig;
            const float b0 = bsum[cl], b1 = bsum[cl + 1];
            float2 v0 = make_float2(acc[mt][nt][0] + b0, acc[mt][nt][1] + b1);
            float2 v1 = make_float2(acc[mt][nt][2] + b0, acc[mt][nt][3] + b1);
            *reinterpret_cast<float2*>(g_xg + (size_t)r0 * GATE + n0 + cl)       = v0;
            *reinterpret_cast<float2*>(g_xg + (size_t)(r0 + 8) * GATE + n0 + cl) = v1;
        }
    }
}

// =============================================================================
// Phase 2: batch-partitioned persistent recurrence (R11 structure, N=8).
// 8 independent groups x 16 CTAs = 128 CTAs. Group bg owns batches
// [8bg, 8bg+8). CTA owns 32 h-cols (128 packed gate rows in registers,
// 8-way k-split across warps — identical fragment math to R11).
// =============================================================================
__device__ __forceinline__ void gbar_flag(int bg) {
    __syncthreads();
    if (threadIdx.x == 0) {
        unsigned* cnt = &g_cnt[bg].v;
        unsigned* gen = &g_gen[bg].v;
        unsigned gv;
        asm volatile("ld.acquire.gpu.global.u32 %0, [%1];" : "=r"(gv) : "l"(gen) : "memory");
        unsigned old;
        asm volatile("atom.acq_rel.gpu.global.add.u32 %0, [%1], %2;"
                     : "=r"(old) : "l"(cnt), "r"(1u) : "memory");
        if (old == GSZ - 1u) {
            asm volatile("st.relaxed.gpu.global.u32 [%0], %1;" :: "l"(cnt), "r"(0u) : "memory");
            asm volatile("st.release.gpu.global.u32 [%0], %1;" :: "l"(gen), "r"(gv + 1u) : "memory");
        } else {
            unsigned cur;
            while (true) {
                asm volatile("ld.acquire.gpu.global.u32 %0, [%1];" : "=r"(cur) : "l"(gen) : "memory");
                if (cur != gv) break;
                __nanosleep(40);
            }
        }
    }
    __syncthreads();
}

template<bool CLUSTER>
__global__ __launch_bounds__(256, 1) void lstm_rec6(const float* __restrict__ Whh,
                                                    float* __restrict__ out)
{
    __shared__ float part[8 * 128 * PPAD];   // 8 planes x 128 rows x 10 = 40960 B
    const int t = threadIdx.x, warp = t >> 5, lane = t & 31;
    const int g = lane >> 2, tig = lane & 3;
    const int bg  = blockIdx.x >> 4;         // batch group 0..7
    const int C0  = (blockIdx.x & 15) * 32;  // h-col base
    const int NB0 = bg * BPG;                // batch base
    const int ks  = warp * 64;               // this warp's k-slice

    // ---- resident W_hh fragments: 128 packed rows, 8-way k-split (as R11) ----
    uint32_t wfr[8][4][4];                   // [mtile][ktile][reg] = 128 regs
#pragma unroll
    for (int mt = 0; mt < 8; mt++) {
        const int row_lo = mt * 16 + g;
        const int row_hi = row_lo + 8;
        const float* wlo = Whh + (size_t)((row_lo >> 5) * 512 + C0 + (row_lo & 31)) * 512;
        const float* whi = Whh + (size_t)((row_hi >> 5) * 512 + C0 + (row_hi & 31)) * 512;
#pragma unroll
        for (int kt = 0; kt < 4; kt++) {
            const int k = ks + kt * 16 + 2 * tig;
            wfr[mt][kt][0] = pack_h2(wlo[k],     wlo[k + 1]);
            wfr[mt][kt][1] = pack_h2(whi[k],     whi[k + 1]);
            wfr[mt][kt][2] = pack_h2(wlo[k + 8], wlo[k + 9]);
            wfr[mt][kt][3] = pack_h2(whi[k + 8], whi[k + 9]);
        }
    }

    // output mapping: thread owns (batch cb, single col)
    const int cb  = t >> 5;                  // 0..7 local batch
    const int col = t & 31;                  // 0..31 local h-col
    const int gb  = NB0 + cb;                // global batch
    const int gc  = C0 + col;                // global h-col

    g_hh[0][gb * HID + gc] = __float2half_rn(0.f);
    float cst = 0.f, hv = 0.f;

    // Xg prefetch for step 0 (4 gate scalars)
    float xg[4];
    {
        const float* xb = g_xg + (size_t)gb * GATE + gc;
#pragma unroll
        for (int q = 0; q < 4; q++) xg[q] = xb[q * 512];
    }

    if (CLUSTER) {
        __syncthreads();
        asm volatile("barrier.cluster.arrive.aligned;" ::: "memory");
        asm volatile("barrier.cluster.wait.aligned;" ::: "memory");
    } else {
        gbar_flag(bg);
    }

    int p = 0;
    for (int s = 0; s < SEQ; s++) {
        const __half* hsrc = g_hh[p];

        // ---- B fragments: h[8 batches, this warp's K=64] from L2 ----
        uint32_t bb[4][2];
        {
            const __half* hp = hsrc + (size_t)(NB0 + g) * HID + ks + 2 * tig;
#pragma unroll
            for (int kt = 0; kt < 4; kt++) {
                bb[kt][0] = ldcg_u32(hp + kt * 16);
                bb[kt][1] = ldcg_u32(hp + kt * 16 + 8);
            }
        }

        // ---- 32 mma: gates[128, 8] partial over this warp's K=64 ----
        float acc[8][4];
#pragma unroll
        for (int mt = 0; mt < 8; mt++)
#pragma unroll
            for (int i = 0; i < 4; i++) acc[mt][i] = 0.f;
#pragma unroll
        for (int kt = 0; kt < 4; kt++)
#pragma unroll
            for (int mt = 0; mt < 8; mt++)
                mma_f16(acc[mt], wfr[mt][kt], bb[kt]);

        // ---- store k-partials: plane[warp] [row 128][batch 8 pad 10] ----
        float* pw = part + warp * (128 * PPAD);
#pragma unroll
        for (int mt = 0; mt < 8; mt++) {
            const int row = mt * 16 + g, bcol = 2 * tig;
            *reinterpret_cast<float2*>(pw + row * PPAD + bcol) =
                make_float2(acc[mt][0], acc[mt][1]);
            *reinterpret_cast<float2*>(pw + (row + 8) * PPAD + bcol) =
                make_float2(acc[mt][2], acc[mt][3]);
        }
        __syncthreads();

        // ---- reduce 8 partials + activations + state update ----
        float sg[4];
#pragma unroll
        for (int q = 0; q < 4; q++) {
            const int base = (q * 32 + col) * PPAD + cb;
            float v = part[base];
#pragma unroll
            for (int w = 1; w < 8; w++) v += part[w * (128 * PPAD) + base];
            sg[q] = v;
        }

        const float iv = sigf(xg[0] + sg[0]);
        const float fv = sigf(xg[1] + sg[1]);
        const float gv = tanhfast(xg[2] + sg[2]);
        const float ov = sigf(xg[3] + sg[3]);

        cst = fv * cst + iv * gv;
        hv  = ov * tanhfast(cst);

        // publish h (must precede arrive), hide DRAM work in the barrier wait
        g_hh[p ^ 1][gb * HID + gc] = __float2half_rn(hv);

        if (CLUSTER) {
            __syncthreads();
            asm volatile("barrier.cluster.arrive.aligned;" ::: "memory");
            out[((size_t)s * BATCH + gb) * HID + gc] = hv;
            if (s + 1 < SEQ) {
                const float* xb = g_xg + ((size_t)(s + 1) * BATCH + gb) * GATE + gc;
#pragma unroll
                for (int q = 0; q < 4; q++) xg[q] = xb[q * 512];
            }
            asm volatile("barrier.cluster.wait.aligned;" ::: "memory");
        } else {
            out[((size_t)s * BATCH + gb) * HID + gc] = hv;
            if (s + 1 < SEQ) {
                const float* xb = g_xg + ((size_t)(s + 1) * BATCH + gb) * GATE + gc;
#pragma unroll
                for (int q = 0; q < 4; q++) xg[q] = xb[q * 512];
            }
            gbar_flag(bg);
        }
        p ^= 1;
    }

    // finals
    float* hf = out + (size_t)SEQ * BATCH * HID;
    float* cf = hf + (size_t)BATCH * HID;
    hf[gb * HID + gc] = hv;
    cf[gb * HID + gc] = cst;
}

// =============================================================================
extern "C" void kernel_launch(void* const* d_in, const int* in_sizes, int n_in,
                              void* d_out, int out_size) {
    const float* x   = (const float*)d_in[0];
    const float* Wih = (const float*)d_in[1];
    const float* Whh = (const float*)d_in[2];
    const float* bih = (const float*)d_in[3];
    const float* bhh = (const float*)d_in[4];
    float* out = (float*)d_out;

    dim3 grid1(16, 1024);
    lstm_xgemm<<<grid1, 256>>>(x, Wih, bih, bhh);

    // Deterministic cluster capability check (same result every call).
    int maxc = 0;
    cudaError_t e = cudaFuncSetAttribute(lstm_rec6<true>,
                                         cudaFuncAttributeNonPortableClusterSizeAllowed, 1);
    if (e == cudaSuccess) {
        cudaLaunchConfig_t qcfg = {};
        qcfg.gridDim = dim3(NG * GSZ, 1, 1);
        qcfg.blockDim = dim3(256, 1, 1);
        qcfg.dynamicSmemBytes = 0;
        if (cudaOccupancyMaxPotentialClusterSize(&maxc, lstm_rec6<true>, &qcfg) != cudaSuccess)
            maxc = 0;
    }

    if (maxc >= GSZ) {
        cudaLaunchConfig_t cfg = {};
        cfg.gridDim = dim3(NG * GSZ, 1, 1);
        cfg.blockDim = dim3(256, 1, 1);
        cfg.dynamicSmemBytes = 0;
        cudaLaunchAttribute attrs[1];
        attrs[0].id = cudaLaunchAttributeClusterDimension;
        attrs[0].val.clusterDim.x = GSZ;
        attrs[0].val.clusterDim.y = 1;
        attrs[0].val.clusterDim.z = 1;
        cfg.attrs = attrs;
        cfg.numAttrs = 1;
        cudaLaunchKernelEx(&cfg, lstm_rec6<true>, Whh, out);
    } else {
        lstm_rec6<false><<<NG * GSZ, 256>>>(Whh, out);
    }
}

// round 15
// speedup vs baseline: 1.2205x; 1.1666x over previous
#include <cuda_runtime.h>
#include <cuda_fp16.h>
#include <cstdint>

#define SEQ   2048
#define BATCH 64
#define DIM   512
#define HID   512
#define GATE  2048   // 4*HID
#define NG    4      // independent batch groups (= clusters)
#define GSZ   16     // CTAs per group (= cluster size)
#define BPG   16     // batches per group

// ---------------- device scratch ---------------------------------------------
__device__ float  g_xg[(size_t)SEQ * BATCH * GATE];  // precomputed input gates
__device__ __half g_hh[2][BATCH * HID];              // double-buffered hidden state (fp16)

struct alignas(128) PadU { unsigned v; unsigned pad[31]; };
__device__ PadU g_cnt[NG];   // fallback barrier: per-group arrive counters
__device__ PadU g_gen[NG];   // fallback barrier: per-group generation (monotonic)

// ---------------- helpers ----------------------------------------------------
__device__ __forceinline__ uint32_t pack_h2(float a, float b) {
    __half2 h = __floats2half2_rn(a, b);
    return *reinterpret_cast<uint32_t*>(&h);
}
__device__ __forceinline__ uint32_t ldcg_u32(const void* p) {
    uint32_t v;
    asm volatile("ld.global.cg.b32 %0, [%1];" : "=r"(v) : "l"(p));
    return v;
}
__device__ __forceinline__ void mma_f16(float* c, const uint32_t* a, const uint32_t* b) {
    asm volatile(
        "mma.sync.aligned.m16n8k16.row.col.f32.f16.f16.f32 "
        "{%0,%1,%2,%3}, {%4,%5,%6,%7}, {%8,%9}, {%0,%1,%2,%3};"
        : "+f"(c[0]), "+f"(c[1]), "+f"(c[2]), "+f"(c[3])
        : "r"(a[0]), "r"(a[1]), "r"(a[2]), "r"(a[3]), "r"(b[0]), "r"(b[1]));
}
__device__ __forceinline__ float sigf(float x) { return 1.0f / (1.0f + __expf(-x)); }
__device__ __forceinline__ float tanhfast(float x) { return 2.0f / (1.0f + __expf(-2.0f * x)) - 1.0f; }

// =============================================================================
// Phase 1: Xg = x @ W_ih^T + (b_ih + b_hh)   (unchanged — proven)
// =============================================================================
__global__ __launch_bounds__(256) void lstm_xgemm(
    const float* __restrict__ x, const float* __restrict__ Wih,
    const float* __restrict__ bih, const float* __restrict__ bhh)
{
    __shared__ __half As[128 * 40];
    __shared__ __half Bs[128 * 40];
    __shared__ float  bsum[128];

    const int t = threadIdx.x;
    const int warp = t >> 5, lane = t & 31;
    const int wm = warp & 1;
    const int wn = warp >> 1;
    const int g = lane >> 2, tig = lane & 3;
    const int m0 = blockIdx.y * 128;
    const int n0 = blockIdx.x * 128;

    if (t < 128) bsum[t] = bih[n0 + t] + bhh[n0 + t];

    float acc[4][4][4];
#pragma unroll
    for (int mt = 0; mt < 4; mt++)
#pragma unroll
        for (int nt = 0; nt < 4; nt++)
#pragma unroll
            for (int i = 0; i < 4; i++) acc[mt][nt][i] = 0.f;

    for (int kc = 0; kc < 512; kc += 32) {
        __syncthreads();
#pragma unroll
        for (int i = 0; i < 4; i++) {
            int f = t + i * 256;
            int row = f >> 3, q = (f & 7) * 4;
            float4 v = *reinterpret_cast<const float4*>(x + (size_t)(m0 + row) * 512 + kc + q);
            __half2* d = reinterpret_cast<__half2*>(As + row * 40 + q);
            d[0] = __floats2half2_rn(v.x, v.y);
            d[1] = __floats2half2_rn(v.z, v.w);
        }
#pragma unroll
        for (int i = 0; i < 4; i++) {
            int f = t + i * 256;
            int row = f >> 3, q = (f & 7) * 4;
            float4 v = *reinterpret_cast<const float4*>(Wih + (size_t)(n0 + row) * 512 + kc + q);
            __half2* d = reinterpret_cast<__half2*>(Bs + row * 40 + q);
            d[0] = __floats2half2_rn(v.x, v.y);
            d[1] = __floats2half2_rn(v.z, v.w);
        }
        __syncthreads();

#pragma unroll
        for (int kt = 0; kt < 2; kt++) {
            const int k0 = kt * 16;
            uint32_t a[4][4], b[4][2];
#pragma unroll
            for (int mt = 0; mt < 4; mt++) {
                const int r = wm * 64 + mt * 16;
                a[mt][0] = *reinterpret_cast<const uint32_t*>(As + (r + g)     * 40 + k0 + 2 * tig);
                a[mt][1] = *reinterpret_cast<const uint32_t*>(As + (r + g + 8) * 40 + k0 + 2 * tig);
                a[mt][2] = *reinterpret_cast<const uint32_t*>(As + (r + g)     * 40 + k0 + 2 * tig + 8);
                a[mt][3] = *reinterpret_cast<const uint32_t*>(As + (r + g + 8) * 40 + k0 + 2 * tig + 8);
            }
#pragma unroll
            for (int nt = 0; nt < 4; nt++) {
                const int rn = wn * 32 + nt * 8;
                b[nt][0] = *reinterpret_cast<const uint32_t*>(Bs + (rn + g) * 40 + k0 + 2 * tig);
                b[nt][1] = *reinterpret_cast<const uint32_t*>(Bs + (rn + g) * 40 + k0 + 2 * tig + 8);
            }
#pragma unroll
            for (int mt = 0; mt < 4; mt++)
#pragma unroll
                for (int nt = 0; nt < 4; nt++)
                    mma_f16(acc[mt][nt], a[mt], b[nt]);
        }
    }

#pragma unroll
    for (int mt = 0; mt < 4; mt++) {
        const int r0 = m0 + wm * 64 + mt * 16 + g;
#pragma unroll
        for (int nt = 0; nt < 4; nt++) {
            const int cl = wn * 32 + nt * 8 + 2 * tig;
            const float b0 = bsum[cl], b1 = bsum[cl + 1];
            float2 v0 = make_float2(acc[mt][nt][0] + b0, acc[mt][nt][1] + b1);
            float2 v1 = make_float2(acc[mt][nt][2] + b0, acc[mt][nt][3] + b1);
            *reinterpret_cast<float2*>(g_xg + (size_t)r0 * GATE + n0 + cl)       = v0;
            *reinterpret_cast<float2*>(g_xg + (size_t)(r0 + 8) * GATE + n0 + cl) = v1;
        }
    }
}

// =============================================================================
// Phase 2: batch-partitioned persistent recurrence. 4 groups x 16 CTAs
// (group == HW cluster when available). Warp tile: 64 rows x K128
// (2-way M x 4-way K split): mh = warp&1, kq = warp>>1.
// 4 partial planes -> 32KB exchange (half of R11), 8 accumulator chains/warp.
// Barrier: split arrive/wait with out-store + Xg prefetch hidden in the wait.
// =============================================================================
__device__ __forceinline__ void gbar_flag(int bg) {
    __syncthreads();
    if (threadIdx.x == 0) {
        unsigned* cnt = &g_cnt[bg].v;
        unsigned* gen = &g_gen[bg].v;
        unsigned gv;
        asm volatile("ld.acquire.gpu.global.u32 %0, [%1];" : "=r"(gv) : "l"(gen) : "memory");
        unsigned old;
        asm volatile("atom.acq_rel.gpu.global.add.u32 %0, [%1], %2;"
                     : "=r"(old) : "l"(cnt), "r"(1u) : "memory");
        if (old == GSZ - 1u) {
            asm volatile("st.relaxed.gpu.global.u32 [%0], %1;" :: "l"(cnt), "r"(0u) : "memory");
            asm volatile("st.release.gpu.global.u32 [%0], %1;" :: "l"(gen), "r"(gv + 1u) : "memory");
        } else {
            unsigned cur;
            while (true) {
                asm volatile("ld.acquire.gpu.global.u32 %0, [%1];" : "=r"(cur) : "l"(gen) : "memory");
                if (cur != gv) break;
                __nanosleep(40);
            }
        }
    }
    __syncthreads();
}

template<bool CLUSTER>
__global__ __launch_bounds__(256, 1) void lstm_rec7(const float* __restrict__ Whh,
                                                    float* __restrict__ out)
{
    __shared__ float part[4 * 128 * 18];   // 4 k-quarter planes = 36864 B
    const int t = threadIdx.x, warp = t >> 5, lane = t & 31;
    const int g = lane >> 2, tig = lane & 3;
    const int bg  = blockIdx.x >> 4;        // batch group 0..3
    const int C0  = (blockIdx.x & 15) * 32; // h-col base
    const int NB0 = bg * BPG;               // batch base
    const int mh  = warp & 1;               // m-half 0..1 (rows [64mh, 64mh+64))
    const int kq  = warp >> 1;              // k-quarter 0..3
    const int ks  = kq * 128;               // this warp's k-slice base

    // ---- resident W_hh fragments: rows [64mh, 64mh+64), K slice 128 ----
    // packed row r = q*32 + j  <->  W_hh[q*512 + C0 + j]
    uint32_t wfr[4][8][4];                  // [mtile][ktile][reg] = 128 regs
#pragma unroll
    for (int mt = 0; mt < 4; mt++) {
        const int row_lo = 64 * mh + mt * 16 + g;
        const int row_hi = row_lo + 8;
        const float* wlo = Whh + (size_t)((row_lo >> 5) * 512 + C0 + (row_lo & 31)) * 512;
        const float* whi = Whh + (size_t)((row_hi >> 5) * 512 + C0 + (row_hi & 31)) * 512;
#pragma unroll
        for (int kt = 0; kt < 8; kt++) {
            const int k = ks + kt * 16 + 2 * tig;
            wfr[mt][kt][0] = pack_h2(wlo[k],     wlo[k + 1]);
            wfr[mt][kt][1] = pack_h2(whi[k],     whi[k + 1]);
            wfr[mt][kt][2] = pack_h2(wlo[k + 8], wlo[k + 9]);
            wfr[mt][kt][3] = pack_h2(whi[k + 8], whi[k + 9]);
        }
    }

    // output mapping: thread owns (batch cb, col pair cp)
    const int cb = t >> 4;                  // 0..15 local batch
    const int cp = t & 15;                  // 0..15 col pair
    const int gb = NB0 + cb;                // global batch
    const int gc = C0 + 2 * cp;             // global h-col

    *reinterpret_cast<uint32_t*>(&g_hh[0][gb * HID + gc]) = 0u;
    float c0 = 0.f, c1 = 0.f, hv0 = 0.f, hv1 = 0.f;

    // Xg prefetch for step 0
    float xg[4][2];
    {
        const float* xb = g_xg + (size_t)gb * GATE + gc;
#pragma unroll
        for (int q = 0; q < 4; q++) {
            float2 u = *reinterpret_cast<const float2*>(xb + q * 512);
            xg[q][0] = u.x; xg[q][1] = u.y;
        }
    }

    if (CLUSTER) {
        __syncthreads();
        asm volatile("barrier.cluster.arrive.aligned;" ::: "memory");
        asm volatile("barrier.cluster.wait.aligned;" ::: "memory");
    } else {
        gbar_flag(bg);
    }

    int p = 0;
    for (int s = 0; s < SEQ; s++) {
        const __half* hsrc = g_hh[p];

        float acc[4][2][4];
#pragma unroll
        for (int mt = 0; mt < 4; mt++)
#pragma unroll
            for (int nt = 0; nt < 2; nt++)
#pragma unroll
                for (int i = 0; i < 4; i++) acc[mt][nt][i] = 0.f;

        // ---- pipelined B-frag loads + mma over 8 k-tiles ----
        uint32_t bb[2][2][2];   // [buf][nt][reg]
#pragma unroll
        for (int nt = 0; nt < 2; nt++) {
            const __half* hp = hsrc + (size_t)(NB0 + nt * 8 + g) * HID + ks + 2 * tig;
            bb[0][nt][0] = ldcg_u32(hp);
            bb[0][nt][1] = ldcg_u32(hp + 8);
        }
#pragma unroll
        for (int kt = 0; kt < 8; kt++) {
            const int cur = kt & 1;
            if (kt < 7) {
#pragma unroll
                for (int nt = 0; nt < 2; nt++) {
                    const __half* hp = hsrc + (size_t)(NB0 + nt * 8 + g) * HID
                                     + ks + (kt + 1) * 16 + 2 * tig;
                    bb[cur ^ 1][nt][0] = ldcg_u32(hp);
                    bb[cur ^ 1][nt][1] = ldcg_u32(hp + 8);
                }
            }
#pragma unroll
            for (int mt = 0; mt < 4; mt++)
#pragma unroll
                for (int nt = 0; nt < 2; nt++)
                    mma_f16(acc[mt][nt], wfr[mt][kt], bb[cur][nt]);
        }

        // ---- store k-partials: plane[kq] rows [64mh, 64mh+64) ----
        float* pw = part + kq * (128 * 18);
#pragma unroll
        for (int mt = 0; mt < 4; mt++)
#pragma unroll
            for (int nt = 0; nt < 2; nt++) {
                const int row = 64 * mh + mt * 16 + g, col = nt * 8 + 2 * tig;
                *reinterpret_cast<float2*>(pw + row * 18 + col) =
                    make_float2(acc[mt][nt][0], acc[mt][nt][1]);
                *reinterpret_cast<float2*>(pw + (row + 8) * 18 + col) =
                    make_float2(acc[mt][nt][2], acc[mt][nt][3]);
            }
        __syncthreads();

        // ---- 4-way reduce + activations + state update ----
        float sg[4][2];
#pragma unroll
        for (int q = 0; q < 4; q++)
#pragma unroll
            for (int jj = 0; jj < 2; jj++) {
                const int base = (q * 32 + 2 * cp + jj) * 18 + cb;
                float v = part[base];
#pragma unroll
                for (int w = 1; w < 4; w++) v += part[w * (128 * 18) + base];
                sg[q][jj] = v;
            }

        const float i0 = sigf(xg[0][0] + sg[0][0]);
        const float i1 = sigf(xg[0][1] + sg[0][1]);
        const float f0 = sigf(xg[1][0] + sg[1][0]);
        const float f1 = sigf(xg[1][1] + sg[1][1]);
        const float g0 = tanhfast(xg[2][0] + sg[2][0]);
        const float g1 = tanhfast(xg[2][1] + sg[2][1]);
        const float o0 = sigf(xg[3][0] + sg[3][0]);
        const float o1 = sigf(xg[3][1] + sg[3][1]);

        c0 = f0 * c0 + i0 * g0;
        c1 = f1 * c1 + i1 * g1;
        hv0 = o0 * tanhfast(c0);
        hv1 = o1 * tanhfast(c1);

        // publish h (must precede arrive)
        *reinterpret_cast<uint32_t*>(&g_hh[p ^ 1][gb * HID + gc]) = pack_h2(hv0, hv1);

        if (CLUSTER) {
            __syncthreads();
            asm volatile("barrier.cluster.arrive.aligned;" ::: "memory");
            // hidden in barrier wait: out store + next-step Xg prefetch
            *reinterpret_cast<float2*>(out + ((size_t)s * BATCH + gb) * HID + gc) =
                make_float2(hv0, hv1);
            if (s + 1 < SEQ) {
                const float* xb = g_xg + ((size_t)(s + 1) * BATCH + gb) * GATE + gc;
#pragma unroll
                for (int q = 0; q < 4; q++) {
                    float2 u = *reinterpret_cast<const float2*>(xb + q * 512);
                    xg[q][0] = u.x; xg[q][1] = u.y;
                }
            }
            asm volatile("barrier.cluster.wait.aligned;" ::: "memory");
        } else {
            *reinterpret_cast<float2*>(out + ((size_t)s * BATCH + gb) * HID + gc) =
                make_float2(hv0, hv1);
            if (s + 1 < SEQ) {
                const float* xb = g_xg + ((size_t)(s + 1) * BATCH + gb) * GATE + gc;
#pragma unroll
                for (int q = 0; q < 4; q++) {
                    float2 u = *reinterpret_cast<const float2*>(xb + q * 512);
                    xg[q][0] = u.x; xg[q][1] = u.y;
                }
            }
            gbar_flag(bg);
        }
        p ^= 1;
    }

    // finals
    float* hf = out + (size_t)SEQ * BATCH * HID;
    float* cf = hf + (size_t)BATCH * HID;
    *reinterpret_cast<float2*>(hf + gb * HID + gc) = make_float2(hv0, hv1);
    *reinterpret_cast<float2*>(cf + gb * HID + gc) = make_float2(c0, c1);
}

// =============================================================================
extern "C" void kernel_launch(void* const* d_in, const int* in_sizes, int n_in,
                              void* d_out, int out_size) {
    const float* x   = (const float*)d_in[0];
    const float* Wih = (const float*)d_in[1];
    const float* Whh = (const float*)d_in[2];
    const float* bih = (const float*)d_in[3];
    const float* bhh = (const float*)d_in[4];
    float* out = (float*)d_out;

    dim3 grid1(16, 1024);
    lstm_xgemm<<<grid1, 256>>>(x, Wih, bih, bhh);

    // Deterministic cluster capability check (same result every call).
    int maxc = 0;
    cudaError_t e = cudaFuncSetAttribute(lstm_rec7<true>,
                                         cudaFuncAttributeNonPortableClusterSizeAllowed, 1);
    if (e == cudaSuccess) {
        cudaLaunchConfig_t qcfg = {};
        qcfg.gridDim = dim3(NG * GSZ, 1, 1);
        qcfg.blockDim = dim3(256, 1, 1);
        qcfg.dynamicSmemBytes = 0;
        if (cudaOccupancyMaxPotentialClusterSize(&maxc, lstm_rec7<true>, &qcfg) != cudaSuccess)
            maxc = 0;
    }

    if (maxc >= GSZ) {
        cudaLaunchConfig_t cfg = {};
        cfg.gridDim = dim3(NG * GSZ, 1, 1);
        cfg.blockDim = dim3(256, 1, 1);
        cfg.dynamicSmemBytes = 0;
        cudaLaunchAttribute attrs[1];
        attrs[0].id = cudaLaunchAttributeClusterDimension;
        attrs[0].val.clusterDim.x = GSZ;
        attrs[0].val.clusterDim.y = 1;
        attrs[0].val.clusterDim.z = 1;
        cfg.attrs = attrs;
        cfg.numAttrs = 1;
        cudaLaunchKernelEx(&cfg, lstm_rec7<true>, Whh, out);
    } else {
        lstm_rec7<false><<<NG * GSZ, 256>>>(Whh, out);
    }
}

// round 16
// speedup vs baseline: 1.2564x; 1.0294x over previous
#include <cuda_runtime.h>
#include <cuda_fp16.h>
#include <cstdint>

#define SEQ   2048
#define BATCH 64
#define DIM   512
#define HID   512
#define GATE  2048   // 4*HID
#define NG    4      // independent batch groups (= clusters)
#define GSZ   16     // CTAs per group (= cluster size)
#define BPG   16     // batches per group

// ---------------- device scratch ---------------------------------------------
__device__ float  g_xg[(size_t)SEQ * BATCH * GATE];  // precomputed input gates
__device__ __half g_hh[2][BATCH * HID];              // double-buffered hidden state (fp16)

struct alignas(128) PadU { unsigned v; unsigned pad[31]; };
__device__ PadU g_cnt[NG];   // fallback barrier: per-group arrive counters
__device__ PadU g_gen[NG];   // fallback barrier: per-group generation (monotonic)

// ---------------- helpers ----------------------------------------------------
__device__ __forceinline__ uint32_t pack_h2(float a, float b) {
    __half2 h = __floats2half2_rn(a, b);
    return *reinterpret_cast<uint32_t*>(&h);
}
__device__ __forceinline__ uint32_t ldcg_u32(const void* p) {
    uint32_t v;
    asm volatile("ld.global.cg.b32 %0, [%1];" : "=r"(v) : "l"(p));
    return v;
}
__device__ __forceinline__ void mma_f16(float* c, const uint32_t* a, const uint32_t* b) {
    asm volatile(
        "mma.sync.aligned.m16n8k16.row.col.f32.f16.f16.f32 "
        "{%0,%1,%2,%3}, {%4,%5,%6,%7}, {%8,%9}, {%0,%1,%2,%3};"
        : "+f"(c[0]), "+f"(c[1]), "+f"(c[2]), "+f"(c[3])
        : "r"(a[0]), "r"(a[1]), "r"(a[2]), "r"(a[3]), "r"(b[0]), "r"(b[1]));
}
__device__ __forceinline__ float sigf(float x) { return 1.0f / (1.0f + __expf(-x)); }
__device__ __forceinline__ float tanhfast(float x) { return 2.0f / (1.0f + __expf(-2.0f * x)) - 1.0f; }
__device__ __forceinline__ uint32_t smem_u32(const void* p) {
    uint32_t a;
    asm("{ .reg .u64 t; cvta.to.shared.u64 t, %1; cvt.u32.u64 %0, t; }" : "=r"(a) : "l"(p));
    return a;
}

// mbarrier cluster protocol ----------------------------------------------------
__device__ __forceinline__ void mbar_init(uint32_t mbar, uint32_t count) {
    asm volatile("mbarrier.init.shared.b64 [%0], %1;" :: "r"(mbar), "r"(count) : "memory");
}
__device__ __forceinline__ void mbar_arrive_remote(uint32_t local_mbar, uint32_t rank) {
    asm volatile(
        "{\n\t.reg .b32 ra;\n\t"
        "mapa.shared::cluster.u32 ra, %0, %1;\n\t"
        "mbarrier.arrive.release.cluster.shared::cluster.b64 _, [ra];\n\t}"
        :: "r"(local_mbar), "r"(rank) : "memory");
}
__device__ __forceinline__ void mbar_wait_cluster(uint32_t mbar, uint32_t parity) {
    asm volatile(
        "{\n\t.reg .pred P;\n\t"
        "W%=:\n\t"
        "mbarrier.try_wait.parity.acquire.cluster.shared::cta.b64 P, [%0], %1;\n\t"
        "@!P bra W%=;\n\t}"
        :: "r"(mbar), "r"(parity) : "memory");
}

// =============================================================================
// Phase 1: Xg = x @ W_ih^T + (b_ih + b_hh)   (unchanged — proven)
// =============================================================================
__global__ __launch_bounds__(256) void lstm_xgemm(
    const float* __restrict__ x, const float* __restrict__ Wih,
    const float* __restrict__ bih, const float* __restrict__ bhh)
{
    __shared__ __half As[128 * 40];
    __shared__ __half Bs[128 * 40];
    __shared__ float  bsum[128];

    const int t = threadIdx.x;
    const int warp = t >> 5, lane = t & 31;
    const int wm = warp & 1;
    const int wn = warp >> 1;
    const int g = lane >> 2, tig = lane & 3;
    const int m0 = blockIdx.y * 128;
    const int n0 = blockIdx.x * 128;

    if (t < 128) bsum[t] = bih[n0 + t] + bhh[n0 + t];

    float acc[4][4][4];
#pragma unroll
    for (int mt = 0; mt < 4; mt++)
#pragma unroll
        for (int nt = 0; nt < 4; nt++)
#pragma unroll
            for (int i = 0; i < 4; i++) acc[mt][nt][i] = 0.f;

    for (int kc = 0; kc < 512; kc += 32) {
        __syncthreads();
#pragma unroll
        for (int i = 0; i < 4; i++) {
            int f = t + i * 256;
            int row = f >> 3, q = (f & 7) * 4;
            float4 v = *reinterpret_cast<const float4*>(x + (size_t)(m0 + row) * 512 + kc + q);
            __half2* d = reinterpret_cast<__half2*>(As + row * 40 + q);
            d[0] = __floats2half2_rn(v.x, v.y);
            d[1] = __floats2half2_rn(v.z, v.w);
        }
#pragma unroll
        for (int i = 0; i < 4; i++) {
            int f = t + i * 256;
            int row = f >> 3, q = (f & 7) * 4;
            float4 v = *reinterpret_cast<const float4*>(Wih + (size_t)(n0 + row) * 512 + kc + q);
            __half2* d = reinterpret_cast<__half2*>(Bs + row * 40 + q);
            d[0] = __floats2half2_rn(v.x, v.y);
            d[1] = __floats2half2_rn(v.z, v.w);
        }
        __syncthreads();

#pragma unroll
        for (int kt = 0; kt < 2; kt++) {
            const int k0 = kt * 16;
            uint32_t a[4][4], b[4][2];
#pragma unroll
            for (int mt = 0; mt < 4; mt++) {
                const int r = wm * 64 + mt * 16;
                a[mt][0] = *reinterpret_cast<const uint32_t*>(As + (r + g)     * 40 + k0 + 2 * tig);
                a[mt][1] = *reinterpret_cast<const uint32_t*>(As + (r + g + 8) * 40 + k0 + 2 * tig);
                a[mt][2] = *reinterpret_cast<const uint32_t*>(As + (r + g)     * 40 + k0 + 2 * tig + 8);
                a[mt][3] = *reinterpret_cast<const uint32_t*>(As + (r + g + 8) * 40 + k0 + 2 * tig + 8);
            }
#pragma unroll
            for (int nt = 0; nt < 4; nt++) {
                const int rn = wn * 32 + nt * 8;
                b[nt][0] = *reinterpret_cast<const uint32_t*>(Bs + (rn + g) * 40 + k0 + 2 * tig);
                b[nt][1] = *reinterpret_cast<const uint32_t*>(Bs + (rn + g) * 40 + k0 + 2 * tig + 8);
            }
#pragma unroll
            for (int mt = 0; mt < 4; mt++)
#pragma unroll
                for (int nt = 0; nt < 4; nt++)
                    mma_f16(acc[mt][nt], a[mt], b[nt]);
        }
    }

#pragma unroll
    for (int mt = 0; mt < 4; mt++) {
        const int r0 = m0 + wm * 64 + mt * 16 + g;
#pragma unroll
        for (int nt = 0; nt < 4; nt++) {
            const int cl = wn * 32 + nt * 8 + 2 * tig;
            const float b0 = bsum[cl], b1 = bsum[cl + 1];
            float2 v0 = make_float2(acc[mt][nt][0] + b0, acc[mt][nt][1] + b1);
            float2 v1 = make_float2(acc[mt][nt][2] + b0, acc[mt][nt][3] + b1);
            *reinterpret_cast<float2*>(g_xg + (size_t)r0 * GATE + n0 + cl)       = v0;
            *reinterpret_cast<float2*>(g_xg + (size_t)(r0 + 8) * GATE + n0 + cl) = v1;
        }
    }
}

// =============================================================================
// Phase 2: batch-partitioned persistent recurrence (R15 body).
// Sync: per-CTA SMEM mbarrier (count=16) + 16 parallel remote arrives
// (mapa + mbarrier.arrive.release.cluster) instead of barrier.cluster.
// =============================================================================
__device__ __forceinline__ void gbar_flag(int bg) {
    __syncthreads();
    if (threadIdx.x == 0) {
        unsigned* cnt = &g_cnt[bg].v;
        unsigned* gen = &g_gen[bg].v;
        unsigned gv;
        asm volatile("ld.acquire.gpu.global.u32 %0, [%1];" : "=r"(gv) : "l"(gen) : "memory");
        unsigned old;
        asm volatile("atom.acq_rel.gpu.global.add.u32 %0, [%1], %2;"
                     : "=r"(old) : "l"(cnt), "r"(1u) : "memory");
        if (old == GSZ - 1u) {
            asm volatile("st.relaxed.gpu.global.u32 [%0], %1;" :: "l"(cnt), "r"(0u) : "memory");
            asm volatile("st.release.gpu.global.u32 [%0], %1;" :: "l"(gen), "r"(gv + 1u) : "memory");
        } else {
            unsigned cur;
            while (true) {
                asm volatile("ld.acquire.gpu.global.u32 %0, [%1];" : "=r"(cur) : "l"(gen) : "memory");
                if (cur != gv) break;
                __nanosleep(40);
            }
        }
    }
    __syncthreads();
}

template<bool CLUSTER>
__global__ __launch_bounds__(256, 1) void lstm_rec8(const float* __restrict__ Whh,
                                                    float* __restrict__ out)
{
    __shared__ float part[4 * 128 * 18];   // 4 k-quarter planes = 36864 B
    __shared__ __align__(8) unsigned long long mbar_store;
    const int t = threadIdx.x, warp = t >> 5, lane = t & 31;
    const int g = lane >> 2, tig = lane & 3;
    const int bg  = blockIdx.x >> 4;        // batch group 0..3
    const int C0  = (blockIdx.x & 15) * 32; // h-col base
    const int NB0 = bg * BPG;               // batch base
    const int mh  = warp & 1;               // m-half (rows [64mh, 64mh+64))
    const int kq  = warp >> 1;              // k-quarter 0..3
    const int ks  = kq * 128;               // k-slice base
    const uint32_t mbar = smem_u32(&mbar_store);

    if (CLUSTER && t == 0) mbar_init(mbar, GSZ);

    // ---- resident W_hh fragments: rows [64mh, 64mh+64), K slice 128 ----
    uint32_t wfr[4][8][4];
#pragma unroll
    for (int mt = 0; mt < 4; mt++) {
        const int row_lo = 64 * mh + mt * 16 + g;
        const int row_hi = row_lo + 8;
        const float* wlo = Whh + (size_t)((row_lo >> 5) * 512 + C0 + (row_lo & 31)) * 512;
        const float* whi = Whh + (size_t)((row_hi >> 5) * 512 + C0 + (row_hi & 31)) * 512;
#pragma unroll
        for (int kt = 0; kt < 8; kt++) {
            const int k = ks + kt * 16 + 2 * tig;
            wfr[mt][kt][0] = pack_h2(wlo[k],     wlo[k + 1]);
            wfr[mt][kt][1] = pack_h2(whi[k],     whi[k + 1]);
            wfr[mt][kt][2] = pack_h2(wlo[k + 8], wlo[k + 9]);
            wfr[mt][kt][3] = pack_h2(whi[k + 8], whi[k + 9]);
        }
    }

    // output mapping: thread owns (batch cb, col pair cp)
    const int cb = t >> 4;
    const int cp = t & 15;
    const int gb = NB0 + cb;
    const int gc = C0 + 2 * cp;

    *reinterpret_cast<uint32_t*>(&g_hh[0][gb * HID + gc]) = 0u;
    float c0 = 0.f, c1 = 0.f, hv0 = 0.f, hv1 = 0.f;

    // Xg prefetch for step 0
    float xg[4][2];
    {
        const float* xb = g_xg + (size_t)gb * GATE + gc;
#pragma unroll
        for (int q = 0; q < 4; q++) {
            float2 u = *reinterpret_cast<const float2*>(xb + q * 512);
            xg[q][0] = u.x; xg[q][1] = u.y;
        }
    }

    // initial barrier: orders h0 stores + all CTAs' mbarrier inits
    if (CLUSTER) {
        __syncthreads();
        asm volatile("barrier.cluster.arrive.aligned;" ::: "memory");
        asm volatile("barrier.cluster.wait.aligned;" ::: "memory");
    } else {
        gbar_flag(bg);
    }

    int p = 0;
    for (int s = 0; s < SEQ; s++) {
        const __half* hsrc = g_hh[p];

        float acc[4][2][4];
#pragma unroll
        for (int mt = 0; mt < 4; mt++)
#pragma unroll
            for (int nt = 0; nt < 2; nt++)
#pragma unroll
                for (int i = 0; i < 4; i++) acc[mt][nt][i] = 0.f;

        // ---- pipelined B-frag loads + mma over 8 k-tiles ----
        uint32_t bb[2][2][2];
#pragma unroll
        for (int nt = 0; nt < 2; nt++) {
            const __half* hp = hsrc + (size_t)(NB0 + nt * 8 + g) * HID + ks + 2 * tig;
            bb[0][nt][0] = ldcg_u32(hp);
            bb[0][nt][1] = ldcg_u32(hp + 8);
        }
#pragma unroll
        for (int kt = 0; kt < 8; kt++) {
            const int cur = kt & 1;
            if (kt < 7) {
#pragma unroll
                for (int nt = 0; nt < 2; nt++) {
                    const __half* hp = hsrc + (size_t)(NB0 + nt * 8 + g) * HID
                                     + ks + (kt + 1) * 16 + 2 * tig;
                    bb[cur ^ 1][nt][0] = ldcg_u32(hp);
                    bb[cur ^ 1][nt][1] = ldcg_u32(hp + 8);
                }
            }
#pragma unroll
            for (int mt = 0; mt < 4; mt++)
#pragma unroll
                for (int nt = 0; nt < 2; nt++)
                    mma_f16(acc[mt][nt], wfr[mt][kt], bb[cur][nt]);
        }

        // ---- store k-partials: plane[kq] rows [64mh, 64mh+64) ----
        float* pw = part + kq * (128 * 18);
#pragma unroll
        for (int mt = 0; mt < 4; mt++)
#pragma unroll
            for (int nt = 0; nt < 2; nt++) {
                const int row = 64 * mh + mt * 16 + g, col = nt * 8 + 2 * tig;
                *reinterpret_cast<float2*>(pw + row * 18 + col) =
                    make_float2(acc[mt][nt][0], acc[mt][nt][1]);
                *reinterpret_cast<float2*>(pw + (row + 8) * 18 + col) =
                    make_float2(acc[mt][nt][2], acc[mt][nt][3]);
            }
        __syncthreads();

        // ---- 4-way reduce + activations + state update ----
        float sg[4][2];
#pragma unroll
        for (int q = 0; q < 4; q++)
#pragma unroll
            for (int jj = 0; jj < 2; jj++) {
                const int base = (q * 32 + 2 * cp + jj) * 18 + cb;
                float v = part[base];
#pragma unroll
                for (int w = 1; w < 4; w++) v += part[w * (128 * 18) + base];
                sg[q][jj] = v;
            }

        const float i0 = sigf(xg[0][0] + sg[0][0]);
        const float i1 = sigf(xg[0][1] + sg[0][1]);
        const float f0 = sigf(xg[1][0] + sg[1][0]);
        const float f1 = sigf(xg[1][1] + sg[1][1]);
        const float g0 = tanhfast(xg[2][0] + sg[2][0]);
        const float g1 = tanhfast(xg[2][1] + sg[2][1]);
        const float o0 = sigf(xg[3][0] + sg[3][0]);
        const float o1 = sigf(xg[3][1] + sg[3][1]);

        c0 = f0 * c0 + i0 * g0;
        c1 = f1 * c1 + i1 * g1;
        hv0 = o0 * tanhfast(c0);
        hv1 = o1 * tanhfast(c1);

        // publish h (before arrives)
        *reinterpret_cast<uint32_t*>(&g_hh[p ^ 1][gb * HID + gc]) = pack_h2(hv0, hv1);

        if (CLUSTER) {
            if (s < SEQ - 1) {
                __syncthreads();   // all h stores issued CTA-wide; part[] consumed
                if (t < GSZ) mbar_arrive_remote(mbar, (uint32_t)t);
                // hidden in wait window: out store + next-step Xg prefetch
                *reinterpret_cast<float2*>(out + ((size_t)s * BATCH + gb) * HID + gc) =
                    make_float2(hv0, hv1);
                {
                    const float* xb = g_xg + ((size_t)(s + 1) * BATCH + gb) * GATE + gc;
#pragma unroll
                    for (int q = 0; q < 4; q++) {
                        float2 u = *reinterpret_cast<const float2*>(xb + q * 512);
                        xg[q][0] = u.x; xg[q][1] = u.y;
                    }
                }
                mbar_wait_cluster(mbar, (uint32_t)(s & 1));
            } else {
                *reinterpret_cast<float2*>(out + ((size_t)s * BATCH + gb) * HID + gc) =
                    make_float2(hv0, hv1);
            }
        } else {
            *reinterpret_cast<float2*>(out + ((size_t)s * BATCH + gb) * HID + gc) =
                make_float2(hv0, hv1);
            if (s + 1 < SEQ) {
                const float* xb = g_xg + ((size_t)(s + 1) * BATCH + gb) * GATE + gc;
#pragma unroll
                for (int q = 0; q < 4; q++) {
                    float2 u = *reinterpret_cast<const float2*>(xb + q * 512);
                    xg[q][0] = u.x; xg[q][1] = u.y;
                }
            }
            gbar_flag(bg);
        }
        p ^= 1;
    }

    // finals
    float* hf = out + (size_t)SEQ * BATCH * HID;
    float* cf = hf + (size_t)BATCH * HID;
    *reinterpret_cast<float2*>(hf + gb * HID + gc) = make_float2(hv0, hv1);
    *reinterpret_cast<float2*>(cf + gb * HID + gc) = make_float2(c0, c1);

    // exit safety: no CTA exits while peer remote arrives may be in flight
    if (CLUSTER) {
        __syncthreads();
        asm volatile("barrier.cluster.arrive.aligned;" ::: "memory");
        asm volatile("barrier.cluster.wait.aligned;" ::: "memory");
    }
}

// =============================================================================
extern "C" void kernel_launch(void* const* d_in, const int* in_sizes, int n_in,
                              void* d_out, int out_size) {
    const float* x   = (const float*)d_in[0];
    const float* Wih = (const float*)d_in[1];
    const float* Whh = (const float*)d_in[2];
    const float* bih = (const float*)d_in[3];
    const float* bhh = (const float*)d_in[4];
    float* out = (float*)d_out;

    dim3 grid1(16, 1024);
    lstm_xgemm<<<grid1, 256>>>(x, Wih, bih, bhh);

    // Deterministic cluster capability check (same result every call).
    int maxc = 0;
    cudaError_t e = cudaFuncSetAttribute(lstm_rec8<true>,
                                         cudaFuncAttributeNonPortableClusterSizeAllowed, 1);
    if (e == cudaSuccess) {
        cudaLaunchConfig_t qcfg = {};
        qcfg.gridDim = dim3(NG * GSZ, 1, 1);
        qcfg.blockDim = dim3(256, 1, 1);
        qcfg.dynamicSmemBytes = 0;
        if (cudaOccupancyMaxPotentialClusterSize(&maxc, lstm_rec8<true>, &qcfg) != cudaSuccess)
            maxc = 0;
    }

    if (maxc >= GSZ) {
        cudaLaunchConfig_t cfg = {};
        cfg.gridDim = dim3(NG * GSZ, 1, 1);
        cfg.blockDim = dim3(256, 1, 1);
        cfg.dynamicSmemBytes = 0;
        cudaLaunchAttribute attrs[1];
        attrs[0].id = cudaLaunchAttributeClusterDimension;
        attrs[0].val.clusterDim.x = GSZ;
        attrs[0].val.clusterDim.y = 1;
        attrs[0].val.clusterDim.z = 1;
        cfg.attrs = attrs;
        cfg.numAttrs = 1;
        cudaLaunchKernelEx(&cfg, lstm_rec8<true>, Whh, out);
    } else {
        lstm_rec8<false><<<NG * GSZ, 256>>>(Whh, out);
    }
}

// round 17
// speedup vs baseline: 1.5826x; 1.2596x over previous
#include <cuda_runtime.h>
#include <cuda_fp16.h>
#include <cstdint>

#define SEQ   2048
#define BATCH 64
#define DIM   512
#define HID   512
#define GATE  2048   // 4*HID
#define NG    4      // independent batch groups (= clusters)
#define GSZ   16     // CTAs per group (= cluster size)
#define BPG   16     // batches per group

// dynamic smem layout (phase 2)
#define SM_HBUF0   0          // 16 KB  incoming h, buffer 0
#define SM_HBUF1   16384      // 16 KB  incoming h, buffer 1
#define SM_PART    32768      // 36864 B k-partial planes
#define SM_SSTAGE  69632      // 2 x 1024 B outgoing slice staging
#define SM_MBAR    71680      // 2 x 8 B mbarriers
#define SM_TOTAL2  71808

// ---------------- device scratch ---------------------------------------------
__device__ float  g_xg[(size_t)SEQ * BATCH * GATE];  // precomputed input gates
__device__ __half g_hh[2][BATCH * HID];              // hidden state (fallback path only)

struct alignas(128) PadU { unsigned v; unsigned pad[31]; };
__device__ PadU g_cnt[NG];   // fallback barrier: per-group arrive counters
__device__ PadU g_gen[NG];   // fallback barrier: per-group generation (monotonic)

// ---------------- helpers ----------------------------------------------------
__device__ __forceinline__ uint32_t pack_h2(float a, float b) {
    __half2 h = __floats2half2_rn(a, b);
    return *reinterpret_cast<uint32_t*>(&h);
}
__device__ __forceinline__ uint32_t ldcg_u32(const void* p) {
    uint32_t v;
    asm volatile("ld.global.cg.b32 %0, [%1];" : "=r"(v) : "l"(p));
    return v;
}
__device__ __forceinline__ uint32_t lds_u32(uint32_t a) {
    uint32_t v;
    asm volatile("ld.shared.b32 %0, [%1];" : "=r"(v) : "r"(a));
    return v;
}
__device__ __forceinline__ void mma_f16(float* c, const uint32_t* a, const uint32_t* b) {
    asm volatile(
        "mma.sync.aligned.m16n8k16.row.col.f32.f16.f16.f32 "
        "{%0,%1,%2,%3}, {%4,%5,%6,%7}, {%8,%9}, {%0,%1,%2,%3};"
        : "+f"(c[0]), "+f"(c[1]), "+f"(c[2]), "+f"(c[3])
        : "r"(a[0]), "r"(a[1]), "r"(a[2]), "r"(a[3]), "r"(b[0]), "r"(b[1]));
}
__device__ __forceinline__ float sigf(float x) { return 1.0f / (1.0f + __expf(-x)); }
__device__ __forceinline__ float tanhfast(float x) { return 2.0f / (1.0f + __expf(-2.0f * x)) - 1.0f; }
__device__ __forceinline__ uint32_t smem_u32(const void* p) {
    uint32_t a;
    asm("{ .reg .u64 t; cvta.to.shared.u64 t, %1; cvt.u32.u64 %0, t; }" : "=r"(a) : "l"(p));
    return a;
}

// mbarrier / DSMEM protocol ----------------------------------------------------
__device__ __forceinline__ void mbar_init(uint32_t mbar, uint32_t count) {
    asm volatile("mbarrier.init.shared.b64 [%0], %1;" :: "r"(mbar), "r"(count) : "memory");
}
__device__ __forceinline__ void mbar_arm(uint32_t mbar, uint32_t bytes) {
    asm volatile("mbarrier.arrive.expect_tx.shared.b64 _, [%0], %1;"
                 :: "r"(mbar), "r"(bytes) : "memory");
}
__device__ __forceinline__ void mbar_wait(uint32_t mbar, uint32_t parity) {
    asm volatile(
        "{\n\t.reg .pred P;\n\t"
        "W%=:\n\t"
        "mbarrier.try_wait.parity.acquire.cluster.shared::cta.b64 P, [%0], %1;\n\t"
        "@!P bra W%=;\n\t}"
        :: "r"(mbar), "r"(parity) : "memory");
}
__device__ __forceinline__ uint32_t mapa_u32(uint32_t addr, uint32_t rank) {
    uint32_t r;
    asm volatile("mapa.shared::cluster.u32 %0, %1, %2;" : "=r"(r) : "r"(addr), "r"(rank));
    return r;
}
__device__ __forceinline__ void bulk_s2s(uint32_t dst_cluster, uint32_t src_local,
                                         uint32_t bytes, uint32_t mbar_cluster) {
    asm volatile(
        "cp.async.bulk.shared::cluster.shared::cta.mbarrier::complete_tx::bytes "
        "[%0], [%1], %2, [%3];"
        :: "r"(dst_cluster), "r"(src_local), "r"(bytes), "r"(mbar_cluster) : "memory");
}

// =============================================================================
// Phase 1: Xg = x @ W_ih^T + (b_ih + b_hh)   (unchanged — proven)
// =============================================================================
__global__ __launch_bounds__(256) void lstm_xgemm(
    const float* __restrict__ x, const float* __restrict__ Wih,
    const float* __restrict__ bih, const float* __restrict__ bhh)
{
    __shared__ __half As[128 * 40];
    __shared__ __half Bs[128 * 40];
    __shared__ float  bsum[128];

    const int t = threadIdx.x;
    const int warp = t >> 5, lane = t & 31;
    const int wm = warp & 1;
    const int wn = warp >> 1;
    const int g = lane >> 2, tig = lane & 3;
    const int m0 = blockIdx.y * 128;
    const int n0 = blockIdx.x * 128;

    if (t < 128) bsum[t] = bih[n0 + t] + bhh[n0 + t];

    float acc[4][4][4];
#pragma unroll
    for (int mt = 0; mt < 4; mt++)
#pragma unroll
        for (int nt = 0; nt < 4; nt++)
#pragma unroll
            for (int i = 0; i < 4; i++) acc[mt][nt][i] = 0.f;

    for (int kc = 0; kc < 512; kc += 32) {
        __syncthreads();
#pragma unroll
        for (int i = 0; i < 4; i++) {
            int f = t + i * 256;
            int row = f >> 3, q = (f & 7) * 4;
            float4 v = *reinterpret_cast<const float4*>(x + (size_t)(m0 + row) * 512 + kc + q);
            __half2* d = reinterpret_cast<__half2*>(As + row * 40 + q);
            d[0] = __floats2half2_rn(v.x, v.y);
            d[1] = __floats2half2_rn(v.z, v.w);
        }
#pragma unroll
        for (int i = 0; i < 4; i++) {
            int f = t + i * 256;
            int row = f >> 3, q = (f & 7) * 4;
            float4 v = *reinterpret_cast<const float4*>(Wih + (size_t)(n0 + row) * 512 + kc + q);
            __half2* d = reinterpret_cast<__half2*>(Bs + row * 40 + q);
            d[0] = __floats2half2_rn(v.x, v.y);
            d[1] = __floats2half2_rn(v.z, v.w);
        }
        __syncthreads();

#pragma unroll
        for (int kt = 0; kt < 2; kt++) {
            const int k0 = kt * 16;
            uint32_t a[4][4], b[4][2];
#pragma unroll
            for (int mt = 0; mt < 4; mt++) {
                const int r = wm * 64 + mt * 16;
                a[mt][0] = *reinterpret_cast<const uint32_t*>(As + (r + g)     * 40 + k0 + 2 * tig);
                a[mt][1] = *reinterpret_cast<const uint32_t*>(As + (r + g + 8) * 40 + k0 + 2 * tig);
                a[mt][2] = *reinterpret_cast<const uint32_t*>(As + (r + g)     * 40 + k0 + 2 * tig + 8);
                a[mt][3] = *reinterpret_cast<const uint32_t*>(As + (r + g + 8) * 40 + k0 + 2 * tig + 8);
            }
#pragma unroll
            for (int nt = 0; nt < 4; nt++) {
                const int rn = wn * 32 + nt * 8;
                b[nt][0] = *reinterpret_cast<const uint32_t*>(Bs + (rn + g) * 40 + k0 + 2 * tig);
                b[nt][1] = *reinterpret_cast<const uint32_t*>(Bs + (rn + g) * 40 + k0 + 2 * tig + 8);
            }
#pragma unroll
            for (int mt = 0; mt < 4; mt++)
#pragma unroll
                for (int nt = 0; nt < 4; nt++)
                    mma_f16(acc[mt][nt], a[mt], b[nt]);
        }
    }

#pragma unroll
    for (int mt = 0; mt < 4; mt++) {
        const int r0 = m0 + wm * 64 + mt * 16 + g;
#pragma unroll
        for (int nt = 0; nt < 4; nt++) {
            const int cl = wn * 32 + nt * 8 + 2 * tig;
            const float b0 = bsum[cl], b1 = bsum[cl + 1];
            float2 v0 = make_float2(acc[mt][nt][0] + b0, acc[mt][nt][1] + b1);
            float2 v1 = make_float2(acc[mt][nt][2] + b0, acc[mt][nt][3] + b1);
            *reinterpret_cast<float2*>(g_xg + (size_t)r0 * GATE + n0 + cl)       = v0;
            *reinterpret_cast<float2*>(g_xg + (size_t)(r0 + 8) * GATE + n0 + cl) = v1;
        }
    }
}

// =============================================================================
// Phase 2: DSMEM h-exchange recurrence. 4 clusters x 16 CTAs.
// hbuf layout: [colgroup 16][batch 16][col 32] fp16 (1 KB contiguous per slice).
// Step: tx-wait on own mbarrier -> mma from local SMEM -> k-partial reduce ->
// act/update -> stage slice -> 16 cp.async.bulk to peers (completion = next sync).
// =============================================================================
__device__ __forceinline__ void gbar_flag(int bg) {
    __syncthreads();
    if (threadIdx.x == 0) {
        unsigned* cnt = &g_cnt[bg].v;
        unsigned* gen = &g_gen[bg].v;
        unsigned gv;
        asm volatile("ld.acquire.gpu.global.u32 %0, [%1];" : "=r"(gv) : "l"(gen) : "memory");
        unsigned old;
        asm volatile("atom.acq_rel.gpu.global.add.u32 %0, [%1], %2;"
                     : "=r"(old) : "l"(cnt), "r"(1u) : "memory");
        if (old == GSZ - 1u) {
            asm volatile("st.relaxed.gpu.global.u32 [%0], %1;" :: "l"(cnt), "r"(0u) : "memory");
            asm volatile("st.release.gpu.global.u32 [%0], %1;" :: "l"(gen), "r"(gv + 1u) : "memory");
        } else {
            unsigned cur;
            while (true) {
                asm volatile("ld.acquire.gpu.global.u32 %0, [%1];" : "=r"(cur) : "l"(gen) : "memory");
                if (cur != gv) break;
                __nanosleep(40);
            }
        }
    }
    __syncthreads();
}

template<bool CLUSTER>
__global__ __launch_bounds__(256, 1) void lstm_rec9(const float* __restrict__ Whh,
                                                    float* __restrict__ out)
{
    extern __shared__ __align__(16) char smem[];
    const uint32_t sb = smem_u32(smem);
    float* part = reinterpret_cast<float*>(smem + SM_PART);

    const int t = threadIdx.x, warp = t >> 5, lane = t & 31;
    const int g = lane >> 2, tig = lane & 3;
    const int bg  = blockIdx.x >> 4;         // batch group 0..3
    const int myrank = blockIdx.x & 15;      // rank within cluster
    const int C0  = myrank * 32;             // h-col base
    const int NB0 = bg * BPG;                // batch base
    const int mh  = warp & 1;                // m-half (rows [64mh, 64mh+64))
    const int kq  = warp >> 1;               // k-quarter 0..3
    const int ks  = kq * 128;                // k-slice base

    const uint32_t hbuf[2]  = { sb + SM_HBUF0, sb + SM_HBUF1 };
    const uint32_t sstage[2] = { sb + SM_SSTAGE, sb + SM_SSTAGE + 1024 };
    const uint32_t mbar[2]  = { sb + SM_MBAR, sb + SM_MBAR + 8 };

    if (CLUSTER && t == 0) {
        mbar_init(mbar[0], 1);
        mbar_init(mbar[1], 1);
        mbar_arm(mbar[0], GSZ * 1024);   // first use: step 2 incoming
        mbar_arm(mbar[1], GSZ * 1024);   // first use: step 1 incoming
    }
    // zero hbuf[0] (h0 = 0)
    if (CLUSTER) {
#pragma unroll
        for (int i = 0; i < 4; i++)
            reinterpret_cast<uint4*>(smem)[t + i * 256] = make_uint4(0u, 0u, 0u, 0u);
    }

    // ---- resident W_hh fragments: rows [64mh, 64mh+64), K slice 128 ----
    uint32_t wfr[4][8][4];
#pragma unroll
    for (int mt = 0; mt < 4; mt++) {
        const int row_lo = 64 * mh + mt * 16 + g;
        const int row_hi = row_lo + 8;
        const float* wlo = Whh + (size_t)((row_lo >> 5) * 512 + C0 + (row_lo & 31)) * 512;
        const float* whi = Whh + (size_t)((row_hi >> 5) * 512 + C0 + (row_hi & 31)) * 512;
#pragma unroll
        for (int kt = 0; kt < 8; kt++) {
            const int k = ks + kt * 16 + 2 * tig;
            wfr[mt][kt][0] = pack_h2(wlo[k],     wlo[k + 1]);
            wfr[mt][kt][1] = pack_h2(whi[k],     whi[k + 1]);
            wfr[mt][kt][2] = pack_h2(wlo[k + 8], wlo[k + 9]);
            wfr[mt][kt][3] = pack_h2(whi[k + 8], whi[k + 9]);
        }
    }

    // output mapping: thread owns (batch cb, col pair cp)
    const int cb = t >> 4;
    const int cp = t & 15;
    const int gb = NB0 + cb;
    const int gc = C0 + 2 * cp;

    if (!CLUSTER) *reinterpret_cast<uint32_t*>(&g_hh[0][gb * HID + gc]) = 0u;
    float c0 = 0.f, c1 = 0.f, hv0 = 0.f, hv1 = 0.f;

    // Xg prefetch for step 0
    float xg[4][2];
    {
        const float* xb = g_xg + (size_t)gb * GATE + gc;
#pragma unroll
        for (int q = 0; q < 4; q++) {
            float2 u = *reinterpret_cast<const float2*>(xb + q * 512);
            xg[q][0] = u.x; xg[q][1] = u.y;
        }
    }

    if (CLUSTER) {
        __syncthreads();
        asm volatile("barrier.cluster.arrive.aligned;" ::: "memory");
        asm volatile("barrier.cluster.wait.aligned;" ::: "memory");
    } else {
        gbar_flag(bg);
    }

    uint32_t par[2] = {0u, 0u};
    int p = 0;
    for (int s = 0; s < SEQ; s++) {
        const int b = s & 1;
        if (CLUSTER) {
            if (s > 0) {
                mbar_wait(mbar[b], par[b]);
                par[b] ^= 1u;
                if (t == 0) mbar_arm(mbar[b], GSZ * 1024);   // re-arm for s+2
            }
        }

        float acc[4][2][4];
#pragma unroll
        for (int mt = 0; mt < 4; mt++)
#pragma unroll
            for (int nt = 0; nt < 2; nt++)
#pragma unroll
                for (int i = 0; i < 4; i++) acc[mt][nt][i] = 0.f;

        if (CLUSTER) {
            // B-frags from local SMEM hbuf[b]: layout [cg][batch][col32]
            const uint32_t hb = hbuf[b];
#pragma unroll
            for (int kt = 0; kt < 8; kt++) {
                const int cg = kq * 4 + (kt >> 1);
                const int kk = (kt & 1) * 16 + 2 * tig;
                uint32_t bb[2][2];
#pragma unroll
                for (int nt = 0; nt < 2; nt++) {
                    const uint32_t a0 = hb + cg * 1024 + (nt * 8 + g) * 64 + kk * 2;
                    bb[nt][0] = lds_u32(a0);
                    bb[nt][1] = lds_u32(a0 + 16);
                }
#pragma unroll
                for (int mt = 0; mt < 4; mt++)
#pragma unroll
                    for (int nt = 0; nt < 2; nt++)
                        mma_f16(acc[mt][nt], wfr[mt][kt], bb[nt]);
            }
        } else {
            const __half* hsrc = g_hh[p];
            uint32_t bb[2][2][2];
#pragma unroll
            for (int nt = 0; nt < 2; nt++) {
                const __half* hp = hsrc + (size_t)(NB0 + nt * 8 + g) * HID + ks + 2 * tig;
                bb[0][nt][0] = ldcg_u32(hp);
                bb[0][nt][1] = ldcg_u32(hp + 8);
            }
#pragma unroll
            for (int kt = 0; kt < 8; kt++) {
                const int cur = kt & 1;
                if (kt < 7) {
#pragma unroll
                    for (int nt = 0; nt < 2; nt++) {
                        const __half* hp = hsrc + (size_t)(NB0 + nt * 8 + g) * HID
                                         + ks + (kt + 1) * 16 + 2 * tig;
                        bb[cur ^ 1][nt][0] = ldcg_u32(hp);
                        bb[cur ^ 1][nt][1] = ldcg_u32(hp + 8);
                    }
                }
#pragma unroll
                for (int mt = 0; mt < 4; mt++)
#pragma unroll
                    for (int nt = 0; nt < 2; nt++)
                        mma_f16(acc[mt][nt], wfr[mt][kt], bb[cur][nt]);
            }
        }

        // ---- store k-partials: plane[kq] rows [64mh, 64mh+64) ----
        float* pw = part + kq * (128 * 18);
#pragma unroll
        for (int mt = 0; mt < 4; mt++)
#pragma unroll
            for (int nt = 0; nt < 2; nt++) {
                const int row = 64 * mh + mt * 16 + g, col = nt * 8 + 2 * tig;
                *reinterpret_cast<float2*>(pw + row * 18 + col) =
                    make_float2(acc[mt][nt][0], acc[mt][nt][1]);
                *reinterpret_cast<float2*>(pw + (row + 8) * 18 + col) =
                    make_float2(acc[mt][nt][2], acc[mt][nt][3]);
            }
        __syncthreads();

        // ---- 4-way reduce + activations + state update ----
        float sg[4][2];
#pragma unroll
        for (int q = 0; q < 4; q++)
#pragma unroll
            for (int jj = 0; jj < 2; jj++) {
                const int base = (q * 32 + 2 * cp + jj) * 18 + cb;
                float v = part[base];
#pragma unroll
                for (int w = 1; w < 4; w++) v += part[w * (128 * 18) + base];
                sg[q][jj] = v;
            }

        const float i0 = sigf(xg[0][0] + sg[0][0]);
        const float i1 = sigf(xg[0][1] + sg[0][1]);
        const float f0 = sigf(xg[1][0] + sg[1][0]);
        const float f1 = sigf(xg[1][1] + sg[1][1]);
        const float g0 = tanhfast(xg[2][0] + sg[2][0]);
        const float g1 = tanhfast(xg[2][1] + sg[2][1]);
        const float o0 = sigf(xg[3][0] + sg[3][0]);
        const float o1 = sigf(xg[3][1] + sg[3][1]);

        c0 = f0 * c0 + i0 * g0;
        c1 = f1 * c1 + i1 * g1;
        hv0 = o0 * tanhfast(c0);
        hv1 = o1 * tanhfast(c1);

        if (CLUSTER) {
            if (s < SEQ - 1) {
                // stage slice [batch16][col32]: thread -> offset cb*64 + cp*4
                const uint32_t sst = sstage[b ^ 1];
                asm volatile("st.shared.b32 [%0], %1;"
                             :: "r"(sst + (uint32_t)(cb * 64 + cp * 4)),
                                "r"(pack_h2(hv0, hv1)) : "memory");
                asm volatile("fence.proxy.async.shared::cta;" ::: "memory");
                __syncthreads();
                if (t < GSZ) {
                    const uint32_t rank = (uint32_t)((myrank + 1 + t) & 15);
                    const uint32_t dst  = mapa_u32(hbuf[b ^ 1], rank) + (uint32_t)(myrank * 1024);
                    const uint32_t mb   = mapa_u32(mbar[b ^ 1], rank);
                    bulk_s2s(dst, sst, 1024, mb);
                }
                // hidden behind arrivals: out store + next Xg prefetch
                *reinterpret_cast<float2*>(out + ((size_t)s * BATCH + gb) * HID + gc) =
                    make_float2(hv0, hv1);
                const float* xb = g_xg + ((size_t)(s + 1) * BATCH + gb) * GATE + gc;
#pragma unroll
                for (int q = 0; q < 4; q++) {
                    float2 u = *reinterpret_cast<const float2*>(xb + q * 512);
                    xg[q][0] = u.x; xg[q][1] = u.y;
                }
            } else {
                *reinterpret_cast<float2*>(out + ((size_t)s * BATCH + gb) * HID + gc) =
                    make_float2(hv0, hv1);
            }
        } else {
            *reinterpret_cast<uint32_t*>(&g_hh[p ^ 1][gb * HID + gc]) = pack_h2(hv0, hv1);
            *reinterpret_cast<float2*>(out + ((size_t)s * BATCH + gb) * HID + gc) =
                make_float2(hv0, hv1);
            if (s + 1 < SEQ) {
                const float* xb = g_xg + ((size_t)(s + 1) * BATCH + gb) * GATE + gc;
#pragma unroll
                for (int q = 0; q < 4; q++) {
                    float2 u = *reinterpret_cast<const float2*>(xb + q * 512);
                    xg[q][0] = u.x; xg[q][1] = u.y;
                }
            }
            gbar_flag(bg);
        }
        p ^= 1;
    }

    // finals
    float* hf = out + (size_t)SEQ * BATCH * HID;
    float* cf = hf + (size_t)BATCH * HID;
    *reinterpret_cast<float2*>(hf + gb * HID + gc) = make_float2(hv0, hv1);
    *reinterpret_cast<float2*>(cf + gb * HID + gc) = make_float2(c0, c1);

    // exit safety: no CTA exits while peers' bulk copies may target our SMEM
    if (CLUSTER) {
        __syncthreads();
        asm volatile("barrier.cluster.arrive.aligned;" ::: "memory");
        asm volatile("barrier.cluster.wait.aligned;" ::: "memory");
    }
}

// =============================================================================
extern "C" void kernel_launch(void* const* d_in, const int* in_sizes, int n_in,
                              void* d_out, int out_size) {
    const float* x   = (const float*)d_in[0];
    const float* Wih = (const float*)d_in[1];
    const float* Whh = (const float*)d_in[2];
    const float* bih = (const float*)d_in[3];
    const float* bhh = (const float*)d_in[4];
    float* out = (float*)d_out;

    dim3 grid1(16, 1024);
    lstm_xgemm<<<grid1, 256>>>(x, Wih, bih, bhh);

    // Deterministic cluster capability check (same result every call).
    int maxc = 0;
    cudaError_t e1 = cudaFuncSetAttribute(lstm_rec9<true>,
                                          cudaFuncAttributeMaxDynamicSharedMemorySize, SM_TOTAL2);
    cudaError_t e2 = cudaFuncSetAttribute(lstm_rec9<true>,
                                          cudaFuncAttributeNonPortableClusterSizeAllowed, 1);
    if (e1 == cudaSuccess && e2 == cudaSuccess) {
        cudaLaunchConfig_t qcfg = {};
        qcfg.gridDim = dim3(NG * GSZ, 1, 1);
        qcfg.blockDim = dim3(256, 1, 1);
        qcfg.dynamicSmemBytes = SM_TOTAL2;
        if (cudaOccupancyMaxPotentialClusterSize(&maxc, lstm_rec9<true>, &qcfg) != cudaSuccess)
            maxc = 0;
    }

    if (maxc >= GSZ) {
        cudaLaunchConfig_t cfg = {};
        cfg.gridDim = dim3(NG * GSZ, 1, 1);
        cfg.blockDim = dim3(256, 1, 1);
        cfg.dynamicSmemBytes = SM_TOTAL2;
        cudaLaunchAttribute attrs[1];
        attrs[0].id = cudaLaunchAttributeClusterDimension;
        attrs[0].val.clusterDim.x = GSZ;
        attrs[0].val.clusterDim.y = 1;
        attrs[0].val.clusterDim.z = 1;
        cfg.attrs = attrs;
        cfg.numAttrs = 1;
        cudaLaunchKernelEx(&cfg, lstm_rec9<true>, Whh, out);
    } else {
        cudaFuncSetAttribute(lstm_rec9<false>,
                             cudaFuncAttributeMaxDynamicSharedMemorySize, SM_TOTAL2);
        lstm_rec9<false><<<NG * GSZ, 256, SM_TOTAL2>>>(Whh, out);
    }
}